// round 14
// baseline (speedup 1.0000x reference)
#include <cuda_runtime.h>
#include <cstdint>

// Gumbel-Sinkhorn, B=16, N=256, TAU=0.1, 100 iterations.
//
// Primal Sinkhorn-Knopp on the constant matrix E = exp(a/tau - m):
//   e[i] = 1 / sum_j E[i][j] * d[j]     (row normalize)
//   d[j] = 1 / sum_i E[i][j] * e[i]     (col normalize)
//   out  = E[i][j] * e[i] * d[j]
// R11: 8-CTA cluster, TWO matrices (A,B) interleaved per cluster (R8 topology,
// 1 row/warp/matrix -> only 16 E regs) with R9's scalar-scatter exchange
// (st.shared::cluster + fence + remote mbarrier arrive, count=7, double
// buffered) and R9's fused col partials. A's DSMEM flight hides behind B's
// reduction and vice versa. Dynamic SMEM (~99KB).

namespace {
constexpr int NMAT    = 16;
constexpr int N       = 256;
constexpr int CSZ     = 8;            // CTAs per cluster
constexpr int ROWS    = N / CSZ;      // 32 rows per CTA per matrix
constexpr int THREADS = 1024;
constexpr int NWARP   = 32;
constexpr int NITER   = 100;
constexpr float INV_TAU = 10.0f;

// dynamic smem layout (bytes)
constexpr uint32_t OFF_DA   = 0;                    // float dA[256]
constexpr uint32_t OFF_DB   = 1024;                 // float dB[256]
constexpr uint32_t OFF_XA   = 2048;                 // float xA[2][8][256]
constexpr uint32_t OFF_XB   = OFF_XA + 16384;       // float xB[2][8][256]
constexpr uint32_t OFF_WSA  = OFF_XB + 16384;       // float wsA[32][256]
constexpr uint32_t OFF_WSB  = OFF_WSA + 32768;      // float wsB[32][256]
constexpr uint32_t OFF_MBA  = OFF_WSB + 32768;      // u64 mbA[2]
constexpr uint32_t OFF_MBB  = OFF_MBA + 16;         // u64 mbB[2]
constexpr uint32_t OFF_RED  = OFF_MBB + 16;         // float redA[32], redB[32]
constexpr uint32_t OFF_MAXB = OFF_RED + 256;        // float mbuf[2][8]
constexpr uint32_t SMEM_TOTAL = OFF_MAXB + 64;      // ~100.7 KB
constexpr uint32_t D_AB = OFF_XB - OFF_XA;          // xA slot -> xB slot delta
constexpr uint32_t D_MB = OFF_MBB - OFF_MBA;        // mbA -> mbB delta
}

__device__ __forceinline__ uint32_t smem_u32(const void* p) {
    return (uint32_t)__cvta_generic_to_shared(p);
}

__device__ __forceinline__ uint32_t mapa_rank(uint32_t laddr, uint32_t rank) {
    uint32_t rem;
    asm volatile("mapa.shared::cluster.u32 %0, %1, %2;" : "=r"(rem) : "r"(laddr), "r"(rank));
    return rem;
}

__device__ __forceinline__ void st_cluster_f32_addr(uint32_t raddr, float v) {
    asm volatile("st.shared::cluster.f32 [%0], %1;" :: "r"(raddr), "f"(v) : "memory");
}

__device__ __forceinline__ void mbar_arrive_cluster(uint32_t raddr) {
    asm volatile("mbarrier.arrive.shared::cluster.b64 _, [%0];" :: "r"(raddr) : "memory");
}

__device__ __forceinline__ void mbar_wait(uint32_t addr, uint32_t phase) {
    asm volatile(
        "{\n\t"
        ".reg .pred P;\n\t"
        "WLOOP_%=:\n\t"
        "mbarrier.try_wait.parity.acquire.cluster.shared::cta.b64 P, [%0], %1, 0x989680;\n\t"
        "@P bra WDONE_%=;\n\t"
        "bra WLOOP_%=;\n\t"
        "WDONE_%=:\n\t"
        "}"
        :: "r"(addr), "r"(phase) : "memory");
}

__device__ __forceinline__ void fence_cluster() {
    asm volatile("fence.acq_rel.cluster;" ::: "memory");
}

__device__ __forceinline__ void cluster_sync_all() {
    asm volatile("barrier.cluster.arrive.aligned;" ::: "memory");
    asm volatile("barrier.cluster.wait.aligned;" ::: "memory");
}

__global__ void __launch_bounds__(THREADS, 1) __cluster_dims__(CSZ, 1, 1)
sinkhorn_kernel(const float* __restrict__ A, float* __restrict__ Out)
{
    extern __shared__ __align__(16) char smem[];
    float* dAp  = reinterpret_cast<float*>(smem + OFF_DA);
    float* dBp  = reinterpret_cast<float*>(smem + OFF_DB);
    float* xAp  = reinterpret_cast<float*>(smem + OFF_XA);   // [2][8][256]
    float* xBp  = reinterpret_cast<float*>(smem + OFF_XB);
    float* wsAp = reinterpret_cast<float*>(smem + OFF_WSA);  // [32][256]
    float* wsBp = reinterpret_cast<float*>(smem + OFF_WSB);
    float* redA = reinterpret_cast<float*>(smem + OFF_RED);
    float* redB = redA + NWARP;
    float* mxb  = reinterpret_cast<float*>(smem + OFF_MAXB); // [2][8]

    const uint32_t sbase = smem_u32(smem);
    const int tid  = threadIdx.x;
    const int w    = tid >> 5;
    const int l    = tid & 31;
    const int rank = blockIdx.x & (CSZ - 1);
    const int cl   = blockIdx.x >> 3;   // cluster id: matrices 2cl, 2cl+1

    const float* AmA = A   + (size_t)(2 * cl)     * N * N;
    const float* AmB = A   + (size_t)(2 * cl + 1) * N * N;
    float*       OmA = Out + (size_t)(2 * cl)     * N * N;
    float*       OmB = Out + (size_t)(2 * cl + 1) * N * N;

    if (tid == 0) {
        #pragma unroll
        for (int q = 0; q < 2; q++) {
            asm volatile("mbarrier.init.shared.b64 [%0], %1;"
                         :: "r"(sbase + OFF_MBA + q * 8), "r"(CSZ - 1) : "memory");
            asm volatile("mbarrier.init.shared.b64 [%0], %1;"
                         :: "r"(sbase + OFF_MBB + q * 8), "r"(CSZ - 1) : "memory");
        }
        asm volatile("fence.mbarrier_init.release.cluster;" ::: "memory");
    }

    // ---- row layout: warp w owns global row rank*32+w; lane l cols [8l,8l+8)
    const int grow = rank * ROWS + w;
    const int c0   = l * 8;

    float erA[8], erB[8];
    {
        float4 a0 = *(const float4*)(AmA + grow * N + c0);
        float4 a1 = *(const float4*)(AmA + grow * N + c0 + 4);
        erA[0]=a0.x; erA[1]=a0.y; erA[2]=a0.z; erA[3]=a0.w;
        erA[4]=a1.x; erA[5]=a1.y; erA[6]=a1.z; erA[7]=a1.w;
        float4 b0 = *(const float4*)(AmB + grow * N + c0);
        float4 b1 = *(const float4*)(AmB + grow * N + c0 + 4);
        erB[0]=b0.x; erB[1]=b0.y; erB[2]=b0.z; erB[3]=b0.w;
        erB[4]=b1.x; erB[5]=b1.y; erB[6]=b1.z; erB[7]=b1.w;
        #pragma unroll
        for (int k = 0; k < 8; k++) { erA[k] *= INV_TAU; erB[k] *= INV_TAU; }
    }

    // ---- per-matrix global max (stable E = exp(a/tau - m))
    {
        float ma = erA[0], mb = erB[0];
        #pragma unroll
        for (int k = 1; k < 8; k++) { ma = fmaxf(ma, erA[k]); mb = fmaxf(mb, erB[k]); }
        #pragma unroll
        for (int off = 16; off; off >>= 1) {
            ma = fmaxf(ma, __shfl_xor_sync(0xffffffffu, ma, off));
            mb = fmaxf(mb, __shfl_xor_sync(0xffffffffu, mb, off));
        }
        if (l == 0) { redA[w] = ma; redB[w] = mb; }
    }
    __syncthreads();
    if (w < 2) {
        float v = (w == 0) ? redA[l] : redB[l];
        #pragma unroll
        for (int off = 16; off; off >>= 1)
            v = fmaxf(v, __shfl_xor_sync(0xffffffffu, v, off));
        if (l == 0) {
            uint32_t slot = sbase + OFF_MAXB + (w * CSZ + rank) * 4;
            #pragma unroll
            for (int r = 0; r < CSZ; r++)
                st_cluster_f32_addr(mapa_rank(slot, (uint32_t)r), v);
        }
    }
    cluster_sync_all();   // orders max stores AND mbarrier inits cluster-wide
    float mA = mxb[0], mB = mxb[CSZ];
    #pragma unroll
    for (int r = 1; r < CSZ; r++) { mA = fmaxf(mA, mxb[r]); mB = fmaxf(mB, mxb[CSZ + r]); }

    #pragma unroll
    for (int k = 0; k < 8; k++) {
        erA[k] = __expf(erA[k] - mA);
        erB[k] = __expf(erB[k] - mB);
    }

    if (tid < N) { dAp[tid] = 1.0f; dBp[tid] = 1.0f; }
    __syncthreads();

    // ---- hoisted remote addresses
    // scatter bases: thread j (<256) pushes its col partial to 7 peers.
    // mapa is offset-preserving within a CTA's window, so xB/parity targets
    // derive from the xA base by constant deltas.
    uint32_t sA[CSZ - 1];
    if (tid < N) {
        uint32_t la = sbase + OFF_XA + (uint32_t)rank * 1024u + (uint32_t)tid * 4u;
        #pragma unroll
        for (int i = 0; i < CSZ - 1; i++)
            sA[i] = mapa_rank(la, (uint32_t)((rank + 1 + i) & (CSZ - 1)));
    }
    uint32_t rmbA = 0;
    if (w == 0 && l < CSZ - 1)
        rmbA = mapa_rank(sbase + OFF_MBA, (uint32_t)((rank + 1 + l) & (CSZ - 1)));

    float rsA = 1.0f, rsB = 1.0f;   // 1/rowsum for my row (persist for epilogue)

    #pragma unroll 1
    for (int it = 0; it < NITER; it++) {
        const uint32_t par    = (uint32_t)(it & 1);
        const uint32_t ph     = (uint32_t)((it >> 1) & 1);
        const uint32_t paroff = par * 8192u;   // [2][8][256] parity stride

        // ======== P1: A row pass + fused col partials ========
        {
            float4 d0 = *(const float4*)&dAp[c0];
            float4 d1 = *(const float4*)&dAp[c0 + 4];
            float s = erA[0]*d0.x + erA[1]*d0.y + erA[2]*d0.z + erA[3]*d0.w
                    + erA[4]*d1.x + erA[5]*d1.y + erA[6]*d1.z + erA[7]*d1.w;
            #pragma unroll
            for (int off = 16; off; off >>= 1)
                s += __shfl_xor_sync(0xffffffffu, s, off);
            rsA = __fdividef(1.0f, fmaxf(s, 1e-30f));
            float4 q0, q1;
            q0.x = erA[0]*rsA; q0.y = erA[1]*rsA; q0.z = erA[2]*rsA; q0.w = erA[3]*rsA;
            q1.x = erA[4]*rsA; q1.y = erA[5]*rsA; q1.z = erA[6]*rsA; q1.w = erA[7]*rsA;
            *(float4*)&wsAp[w * N + c0]     = q0;
            *(float4*)&wsAp[w * N + c0 + 4] = q1;
        }
        __syncthreads();

        // ======== P2: B row pass (all warps) || colsumA + scatterA (w 0-7) ==
        {
            float4 d0 = *(const float4*)&dBp[c0];
            float4 d1 = *(const float4*)&dBp[c0 + 4];
            float s = erB[0]*d0.x + erB[1]*d0.y + erB[2]*d0.z + erB[3]*d0.w
                    + erB[4]*d1.x + erB[5]*d1.y + erB[6]*d1.z + erB[7]*d1.w;
            #pragma unroll
            for (int off = 16; off; off >>= 1)
                s += __shfl_xor_sync(0xffffffffu, s, off);
            rsB = __fdividef(1.0f, fmaxf(s, 1e-30f));
            float4 q0, q1;
            q0.x = erB[0]*rsB; q0.y = erB[1]*rsB; q0.z = erB[2]*rsB; q0.w = erB[3]*rsB;
            q1.x = erB[4]*rsB; q1.y = erB[5]*rsB; q1.z = erB[6]*rsB; q1.w = erB[7]*rsB;
            *(float4*)&wsBp[w * N + c0]     = q0;
            *(float4*)&wsBp[w * N + c0 + 4] = q1;
        }
        float pownA = 0.0f;
        if (tid < N) {
            float f0 = 0.f, f1 = 0.f, f2 = 0.f, f3 = 0.f;
            #pragma unroll
            for (int w2 = 0; w2 < NWARP; w2 += 4) {
                f0 += wsAp[w2 * N + tid];       f1 += wsAp[(w2 + 1) * N + tid];
                f2 += wsAp[(w2 + 2) * N + tid]; f3 += wsAp[(w2 + 3) * N + tid];
            }
            pownA = (f0 + f1) + (f2 + f3);
            #pragma unroll
            for (int i = 0; i < CSZ - 1; i++)
                st_cluster_f32_addr(sA[i] + paroff, pownA);
        }
        __syncthreads();

        // ======== P3: publish A || colsumB + scatterB ========
        if (w == 0 && l < CSZ - 1) {
            fence_cluster();
            mbar_arrive_cluster(rmbA + par * 8);
        }
        float pownB = 0.0f;
        if (tid < N) {
            float f0 = 0.f, f1 = 0.f, f2 = 0.f, f3 = 0.f;
            #pragma unroll
            for (int w2 = 0; w2 < NWARP; w2 += 4) {
                f0 += wsBp[w2 * N + tid];       f1 += wsBp[(w2 + 1) * N + tid];
                f2 += wsBp[(w2 + 2) * N + tid]; f3 += wsBp[(w2 + 3) * N + tid];
            }
            pownB = (f0 + f1) + (f2 + f3);
            #pragma unroll
            for (int i = 0; i < CSZ - 1; i++)
                st_cluster_f32_addr(sA[i] + D_AB + paroff, pownB);
        }
        __syncthreads();

        // ======== P4: publish B || combine A then B (warps 0-7) ========
        if (w == 0 && l < CSZ - 1) {
            fence_cluster();
            mbar_arrive_cluster(rmbA + D_MB + par * 8);
        }
        if (tid < N) {
            // A's exchange has been in flight since P3 start -> near-free wait
            mbar_wait(sbase + OFF_MBA + par * 8, ph);
            float fa = pownA;
            #pragma unroll
            for (int i = 1; i < CSZ; i++) {
                int src = (rank + i) & (CSZ - 1);
                fa += xAp[paroff / 4 + src * N + tid];
            }
            dAp[tid] = __fdividef(1.0f, fmaxf(fa, 1e-30f));

            mbar_wait(sbase + OFF_MBB + par * 8, ph);
            float fb = pownB;
            #pragma unroll
            for (int i = 1; i < CSZ; i++) {
                int src = (rank + i) & (CSZ - 1);
                fb += xBp[paroff / 4 + src * N + tid];
            }
            dBp[tid] = __fdividef(1.0f, fmaxf(fb, 1e-30f));
        }
        __syncthreads();
    }

    // ======== epilogue: P = E * e[i] * d[j] for both matrices ========
    {
        float4 d0 = *(const float4*)&dAp[c0];
        float4 d1 = *(const float4*)&dAp[c0 + 4];
        float4 o0, o1;
        o0.x = erA[0]*rsA*d0.x; o0.y = erA[1]*rsA*d0.y;
        o0.z = erA[2]*rsA*d0.z; o0.w = erA[3]*rsA*d0.w;
        o1.x = erA[4]*rsA*d1.x; o1.y = erA[5]*rsA*d1.y;
        o1.z = erA[6]*rsA*d1.z; o1.w = erA[7]*rsA*d1.w;
        *(float4*)(OmA + grow * N + c0)     = o0;
        *(float4*)(OmA + grow * N + c0 + 4) = o1;
    }
    {
        float4 d0 = *(const float4*)&dBp[c0];
        float4 d1 = *(const float4*)&dBp[c0 + 4];
        float4 o0, o1;
        o0.x = erB[0]*rsB*d0.x; o0.y = erB[1]*rsB*d0.y;
        o0.z = erB[2]*rsB*d0.z; o0.w = erB[3]*rsB*d0.w;
        o1.x = erB[4]*rsB*d1.x; o1.y = erB[5]*rsB*d1.y;
        o1.z = erB[6]*rsB*d1.z; o1.w = erB[7]*rsB*d1.w;
        *(float4*)(OmB + grow * N + c0)     = o0;
        *(float4*)(OmB + grow * N + c0 + 4) = o1;
    }

    // keep all CTAs alive until every in-flight remote store is consumed
    cluster_sync_all();
}

extern "C" void kernel_launch(void* const* d_in, const int* in_sizes, int n_in,
                              void* d_out, int out_size) {
    const float* alpha = (const float*)d_in[0];
    float* out = (float*)d_out;
    cudaFuncSetAttribute(sinkhorn_kernel,
                         cudaFuncAttributeMaxDynamicSharedMemorySize, SMEM_TOTAL);
    sinkhorn_kernel<<<(NMAT / 2) * CSZ, THREADS, SMEM_TOTAL>>>(alpha, out);
}

// round 15
// speedup vs baseline: 1.0716x; 1.0716x over previous
#include <cuda_runtime.h>
#include <cstdint>

// Gumbel-Sinkhorn, B=16, N=256, TAU=0.1, 100 iterations.
//
// Primal Sinkhorn-Knopp on the constant matrix E = exp(a/tau - m):
//   e[i] = 1 / sum_j E[i][j] * d[j]     (row normalize)
//   d[j] = 1 / sum_i E[i][j] * e[i]     (col normalize)
//   out  = E[i][j] * e[i] * d[j]
// R12: 2-CTA cluster (minimal comm). 128 rows/CTA, 4 rows/warp, E in ROW
// layout registers only (er[32]); col partials fused from row sums (R9).
// Exchange per iter: each column-owner lane pushes ONE float to ONE peer
// (st.shared::cluster), published by a single mbarrier.arrive.release.cluster
// (count=1, cumulativity over the preceding __syncthreads), one try_wait,
// combine = own + peer. Double-buffered parity. No fence, no bulk engine.

namespace {
constexpr int NMAT    = 16;
constexpr int N       = 256;
constexpr int CSZ     = 2;            // CTAs per cluster (one matrix)
constexpr int ROWS    = N / CSZ;      // 128 rows per CTA
constexpr int THREADS = 1024;
constexpr int NWARP   = 32;
constexpr int RPW     = 4;            // rows per warp
constexpr int NITER   = 100;
constexpr int WSL     = 264;          // ws row length (16B aligned, conflict-free)
constexpr float INV_TAU = 10.0f;
}

__device__ __forceinline__ uint32_t smem_u32(const void* p) {
    return (uint32_t)__cvta_generic_to_shared(p);
}

__device__ __forceinline__ uint32_t mapa_rank(uint32_t laddr, uint32_t rank) {
    uint32_t rem;
    asm volatile("mapa.shared::cluster.u32 %0, %1, %2;" : "=r"(rem) : "r"(laddr), "r"(rank));
    return rem;
}

__device__ __forceinline__ void st_cluster_f32_addr(uint32_t raddr, float v) {
    asm volatile("st.shared::cluster.f32 [%0], %1;" :: "r"(raddr), "f"(v) : "memory");
}

// Remote arrive with explicit cluster-scope RELEASE: publishes (via
// cumulativity over the preceding CTA barrier) all threads' prior stores,
// including weak st.shared::cluster to the peer. Pairs with the acquire
// in mbar_wait.
__device__ __forceinline__ void mbar_arrive_release(uint32_t raddr) {
    asm volatile("mbarrier.arrive.release.cluster.shared::cluster.b64 _, [%0];"
                 :: "r"(raddr) : "memory");
}

__device__ __forceinline__ void mbar_wait(uint32_t addr, uint32_t phase) {
    asm volatile(
        "{\n\t"
        ".reg .pred P;\n\t"
        "WLOOP_%=:\n\t"
        "mbarrier.try_wait.parity.acquire.cluster.shared::cta.b64 P, [%0], %1, 0x989680;\n\t"
        "@P bra WDONE_%=;\n\t"
        "bra WLOOP_%=;\n\t"
        "WDONE_%=:\n\t"
        "}"
        :: "r"(addr), "r"(phase) : "memory");
}

__device__ __forceinline__ void cluster_sync_all() {
    asm volatile("barrier.cluster.arrive.aligned;" ::: "memory");
    asm volatile("barrier.cluster.wait.aligned;" ::: "memory");
}

__global__ void __launch_bounds__(THREADS, 1) __cluster_dims__(CSZ, 1, 1)
sinkhorn_kernel(const float* __restrict__ A, float* __restrict__ Out)
{
    __shared__ __align__(16) float d_vec[N];
    __shared__ __align__(16) float ws[NWARP][WSL];   // col-partial workspace
    __shared__ __align__(16) float xrecv[2][N];      // peer partial (parity)
    __shared__ __align__(8) unsigned long long mbar[2];
    __shared__ float red_sh[NWARP];
    __shared__ float mbuf[CSZ];

    const int tid  = threadIdx.x;
    const int w    = tid >> 5;
    const int l    = tid & 31;
    const int rank = blockIdx.x & (CSZ - 1);
    const int b    = blockIdx.x >> 1;
    const uint32_t peer = (uint32_t)(rank ^ 1);

    const float* Am = A   + (size_t)b * N * N;
    float*       Om = Out + (size_t)b * N * N;

    if (tid == 0) {
        asm volatile("mbarrier.init.shared.b64 [%0], 1;"
                     :: "r"(smem_u32(&mbar[0])) : "memory");
        asm volatile("mbarrier.init.shared.b64 [%0], 1;"
                     :: "r"(smem_u32(&mbar[1])) : "memory");
        asm volatile("fence.mbarrier_init.release.cluster;" ::: "memory");
    }

    // ---- row layout: warp w owns local rows [4w,4w+4); lane l cols [8l,8l+8)
    const int c0   = l * 8;
    const int grow = rank * ROWS + RPW * w;   // global row of first owned row

    float er[32];   // er[r*8+k] : row r (0..3), col c0+k
    #pragma unroll
    for (int r = 0; r < RPW; r++) {
        float4 a0 = *(const float4*)(Am + (grow + r) * N + c0);
        float4 a1 = *(const float4*)(Am + (grow + r) * N + c0 + 4);
        er[r*8+0]=a0.x; er[r*8+1]=a0.y; er[r*8+2]=a0.z; er[r*8+3]=a0.w;
        er[r*8+4]=a1.x; er[r*8+5]=a1.y; er[r*8+6]=a1.z; er[r*8+7]=a1.w;
    }
    #pragma unroll
    for (int k = 0; k < 32; k++) er[k] *= INV_TAU;

    // ---- global max m (stable E = exp(a/tau - m))
    {
        float mx = er[0];
        #pragma unroll
        for (int k = 1; k < 32; k++) mx = fmaxf(mx, er[k]);
        #pragma unroll
        for (int off = 16; off; off >>= 1)
            mx = fmaxf(mx, __shfl_xor_sync(0xffffffffu, mx, off));
        if (l == 0) red_sh[w] = mx;
    }
    __syncthreads();
    if (w == 0) {
        float v = red_sh[l];
        #pragma unroll
        for (int off = 16; off; off >>= 1)
            v = fmaxf(v, __shfl_xor_sync(0xffffffffu, v, off));
        if (l == 0) {
            uint32_t slot = smem_u32(&mbuf[rank]);
            st_cluster_f32_addr(mapa_rank(slot, 0), v);
            st_cluster_f32_addr(mapa_rank(slot, 1), v);
        }
    }
    cluster_sync_all();   // orders max stores AND mbarrier inits cluster-wide
    const float m = fmaxf(mbuf[0], mbuf[1]);

    #pragma unroll
    for (int k = 0; k < 32; k++) er[k] = __expf(er[k] - m);

    if (tid < N) d_vec[tid] = 1.0f;   // c = 0 initially
    __syncthreads();

    // ---- hoisted remote addresses
    const int j = tid >> 2;           // column owned for colsum/combine
    const int g = tid & 3;            // depth slice within colsum
    const uint32_t mb_local = smem_u32(&mbar[0]);
    uint32_t raddr = 0, rmb = 0;
    if (g == 0) raddr = mapa_rank(smem_u32(&xrecv[0][j]), peer);
    if (tid == 0) rmb = mapa_rank(mb_local, peer);

    float rs0 = 1.0f, rs1 = 1.0f, rs2 = 1.0f, rs3 = 1.0f;

    #pragma unroll 1
    for (int it = 0; it < NITER; it++) {
        const uint32_t par = (uint32_t)(it & 1);
        const uint32_t ph  = (uint32_t)((it >> 1) & 1);

        // ======== row pass: 4 rows/warp ========
        {
            float4 d0 = *(const float4*)&d_vec[c0];
            float4 d1 = *(const float4*)&d_vec[c0 + 4];
            float s0 = er[0]*d0.x + er[1]*d0.y + er[2]*d0.z + er[3]*d0.w
                     + er[4]*d1.x + er[5]*d1.y + er[6]*d1.z + er[7]*d1.w;
            float s1 = er[8]*d0.x + er[9]*d0.y + er[10]*d0.z + er[11]*d0.w
                     + er[12]*d1.x + er[13]*d1.y + er[14]*d1.z + er[15]*d1.w;
            float s2 = er[16]*d0.x + er[17]*d0.y + er[18]*d0.z + er[19]*d0.w
                     + er[20]*d1.x + er[21]*d1.y + er[22]*d1.z + er[23]*d1.w;
            float s3 = er[24]*d0.x + er[25]*d0.y + er[26]*d0.z + er[27]*d0.w
                     + er[28]*d1.x + er[29]*d1.y + er[30]*d1.z + er[31]*d1.w;
            #pragma unroll
            for (int off = 16; off; off >>= 1) {
                s0 += __shfl_xor_sync(0xffffffffu, s0, off);
                s1 += __shfl_xor_sync(0xffffffffu, s1, off);
                s2 += __shfl_xor_sync(0xffffffffu, s2, off);
                s3 += __shfl_xor_sync(0xffffffffu, s3, off);
            }
            rs0 = __fdividef(1.0f, fmaxf(s0, 1e-30f));
            rs1 = __fdividef(1.0f, fmaxf(s1, 1e-30f));
            rs2 = __fdividef(1.0f, fmaxf(s2, 1e-30f));
            rs3 = __fdividef(1.0f, fmaxf(s3, 1e-30f));

            // fused col partials for my 4 rows
            float4 q0, q1;
            q0.x = er[0]*rs0 + er[8]*rs1  + er[16]*rs2 + er[24]*rs3;
            q0.y = er[1]*rs0 + er[9]*rs1  + er[17]*rs2 + er[25]*rs3;
            q0.z = er[2]*rs0 + er[10]*rs1 + er[18]*rs2 + er[26]*rs3;
            q0.w = er[3]*rs0 + er[11]*rs1 + er[19]*rs2 + er[27]*rs3;
            q1.x = er[4]*rs0 + er[12]*rs1 + er[20]*rs2 + er[28]*rs3;
            q1.y = er[5]*rs0 + er[13]*rs1 + er[21]*rs2 + er[29]*rs3;
            q1.z = er[6]*rs0 + er[14]*rs1 + er[22]*rs2 + er[30]*rs3;
            q1.w = er[7]*rs0 + er[15]*rs1 + er[23]*rs2 + er[31]*rs3;
            *(float4*)&ws[w][c0]     = q0;
            *(float4*)&ws[w][c0 + 4] = q1;
        }
        __syncthreads();

        // ======== colsum over 32 warp-rows (4 threads/col, 8 each) ========
        // ws[g + 4i][j]: conflict-free banks (WSL=264 => bank = 8g + j mod 32)
        float p;
        {
            float f0 = ws[g][j]      + ws[g + 4][j];
            float f1 = ws[g + 8][j]  + ws[g + 12][j];
            float f2 = ws[g + 16][j] + ws[g + 20][j];
            float f3 = ws[g + 24][j] + ws[g + 28][j];
            p = (f0 + f1) + (f2 + f3);
            p += __shfl_xor_sync(0xffffffffu, p, 1);
            p += __shfl_xor_sync(0xffffffffu, p, 2);
            if (g == 0) st_cluster_f32_addr(raddr + par * 1024u, p);
        }
        __syncthreads();   // all remote stores happened-before the arrive

        // ======== publish + combine ========
        if (tid == 0) mbar_arrive_release(rmb + par * 8);
        if (g == 0) {
            mbar_wait(mb_local + par * 8, ph);
            float f = p + xrecv[par][j];
            d_vec[j] = __fdividef(1.0f, fmaxf(f, 1e-30f));
        }
        __syncthreads();
    }

    // ======== epilogue: P = E * e[i] * d[j] (4 rows/warp) ========
    {
        float4 d0 = *(const float4*)&d_vec[c0];
        float4 d1 = *(const float4*)&d_vec[c0 + 4];
        float rs[RPW] = {rs0, rs1, rs2, rs3};
        #pragma unroll
        for (int r = 0; r < RPW; r++) {
            float4 o;
            o.x = er[r*8+0]*rs[r]*d0.x; o.y = er[r*8+1]*rs[r]*d0.y;
            o.z = er[r*8+2]*rs[r]*d0.z; o.w = er[r*8+3]*rs[r]*d0.w;
            *(float4*)(Om + (grow + r) * N + c0) = o;
            o.x = er[r*8+4]*rs[r]*d1.x; o.y = er[r*8+5]*rs[r]*d1.y;
            o.z = er[r*8+6]*rs[r]*d1.z; o.w = er[r*8+7]*rs[r]*d1.w;
            *(float4*)(Om + (grow + r) * N + c0 + 4) = o;
        }
    }

    // keep both CTAs alive until every in-flight remote store is consumed
    cluster_sync_all();
}

extern "C" void kernel_launch(void* const* d_in, const int* in_sizes, int n_in,
                              void* d_out, int out_size) {
    const float* alpha = (const float*)d_in[0];
    float* out = (float*)d_out;
    sinkhorn_kernel<<<NMAT * CSZ, THREADS>>>(alpha, out);
}

// round 16
// speedup vs baseline: 1.1308x; 1.0552x over previous
#include <cuda_runtime.h>
#include <cstdint>

// Gumbel-Sinkhorn, B=16, N=256, TAU=0.1, 100 iterations.
//
// Primal Sinkhorn-Knopp on the constant matrix E = exp(a/tau - m):
//   e[i] = 1 / sum_j E[i][j] * d[j]     (row normalize)
//   d[j] = 1 / sum_i E[i][j] * e[i]     (col normalize)
//   out  = E[i][j] * e[i] * d[j]
// R13: R9 layout (4-CTA cluster, 64 rows/CTA, er[16] row-layout regs, fused
// col partials) with a decentralized publish: each warp scatters its 8
// column partials to the 3 peers, __syncwarp, lane 0 issues 3 remote
// mbarrier.arrive.release.cluster (count = 3*32 = 96). No CTA-wide publish
// barrier, no cluster fence; arrive flight overlaps other warps' reductions.
// 2 __syncthreads per iteration. Colsum: 4 threads/col, 8 LDS + 2 shfl,
// conflict-free via 264-float ws rows.

namespace {
constexpr int NMAT    = 16;
constexpr int N       = 256;
constexpr int CSZ     = 4;            // CTAs per cluster (one matrix)
constexpr int ROWS    = N / CSZ;      // 64 rows per CTA
constexpr int THREADS = 1024;
constexpr int NWARP   = 32;
constexpr int NITER   = 100;
constexpr int WSL     = 264;          // padded ws row (conflict-free colsum)
constexpr int ARR_CNT = (CSZ - 1) * NWARP;   // 96 arrives per phase
constexpr float INV_TAU = 10.0f;
}

__device__ __forceinline__ uint32_t smem_u32(const void* p) {
    return (uint32_t)__cvta_generic_to_shared(p);
}

__device__ __forceinline__ uint32_t mapa_rank(uint32_t laddr, uint32_t rank) {
    uint32_t rem;
    asm volatile("mapa.shared::cluster.u32 %0, %1, %2;" : "=r"(rem) : "r"(laddr), "r"(rank));
    return rem;
}

__device__ __forceinline__ void st_cluster_f32_addr(uint32_t raddr, float v) {
    asm volatile("st.shared::cluster.f32 [%0], %1;" :: "r"(raddr), "f"(v) : "memory");
}

// Remote arrive with cluster-scope RELEASE: cumulativity over the preceding
// __syncwarp publishes the warp's prior st.shared::cluster stores. Pairs
// with the acquire in mbar_wait. (Correctness of arrive.release validated R12.)
__device__ __forceinline__ void mbar_arrive_release(uint32_t raddr) {
    asm volatile("mbarrier.arrive.release.cluster.shared::cluster.b64 _, [%0];"
                 :: "r"(raddr) : "memory");
}

__device__ __forceinline__ void mbar_wait(uint32_t addr, uint32_t phase) {
    asm volatile(
        "{\n\t"
        ".reg .pred P;\n\t"
        "WLOOP_%=:\n\t"
        "mbarrier.try_wait.parity.acquire.cluster.shared::cta.b64 P, [%0], %1, 0x989680;\n\t"
        "@P bra WDONE_%=;\n\t"
        "bra WLOOP_%=;\n\t"
        "WDONE_%=:\n\t"
        "}"
        :: "r"(addr), "r"(phase) : "memory");
}

__device__ __forceinline__ void cluster_sync_all() {
    asm volatile("barrier.cluster.arrive.aligned;" ::: "memory");
    asm volatile("barrier.cluster.wait.aligned;" ::: "memory");
}

__global__ void __launch_bounds__(THREADS, 1) __cluster_dims__(CSZ, 1, 1)
sinkhorn_kernel(const float* __restrict__ A, float* __restrict__ Out)
{
    __shared__ __align__(16) float d_vec[N];
    __shared__ __align__(16) float ws[NWARP][WSL];   // col partials, ~33.8 KB
    __shared__ __align__(16) float xbuf[2][CSZ][N];  // peer partials, 8 KB
    __shared__ __align__(8) unsigned long long mbar[2];
    __shared__ float red_sh[NWARP];
    __shared__ float mbuf[CSZ];

    const int tid  = threadIdx.x;
    const int w    = tid >> 5;
    const int l    = tid & 31;
    const int rank = blockIdx.x & (CSZ - 1);
    const int b    = blockIdx.x >> 2;

    const float* Am = A   + (size_t)b * N * N;
    float*       Om = Out + (size_t)b * N * N;

    if (tid == 0) {
        asm volatile("mbarrier.init.shared.b64 [%0], %1;"
                     :: "r"(smem_u32(&mbar[0])), "r"(ARR_CNT) : "memory");
        asm volatile("mbarrier.init.shared.b64 [%0], %1;"
                     :: "r"(smem_u32(&mbar[1])), "r"(ARR_CNT) : "memory");
        asm volatile("fence.mbarrier_init.release.cluster;" ::: "memory");
    }

    // ---- row layout: warp w owns local rows {2w, 2w+1}; lane l cols [8l,8l+8)
    const int r0   = 2 * w;
    const int c0   = l * 8;
    const int grow = rank * ROWS + r0;

    float er[16];  // [row r0: 8 cols][row r0+1: 8 cols]
    {
        float4 a0 = *(const float4*)(Am + grow * N + c0);
        float4 a1 = *(const float4*)(Am + grow * N + c0 + 4);
        float4 b0 = *(const float4*)(Am + (grow + 1) * N + c0);
        float4 b1 = *(const float4*)(Am + (grow + 1) * N + c0 + 4);
        er[0]=a0.x; er[1]=a0.y; er[2]=a0.z;  er[3]=a0.w;
        er[4]=a1.x; er[5]=a1.y; er[6]=a1.z;  er[7]=a1.w;
        er[8]=b0.x; er[9]=b0.y; er[10]=b0.z; er[11]=b0.w;
        er[12]=b1.x; er[13]=b1.y; er[14]=b1.z; er[15]=b1.w;
        #pragma unroll
        for (int k = 0; k < 16; k++) er[k] *= INV_TAU;
    }

    // ---- global per-matrix max m (stable E = exp(a/tau - m))
    {
        float mx = er[0];
        #pragma unroll
        for (int k = 1; k < 16; k++) mx = fmaxf(mx, er[k]);
        #pragma unroll
        for (int off = 16; off; off >>= 1)
            mx = fmaxf(mx, __shfl_xor_sync(0xffffffffu, mx, off));
        if (l == 0) red_sh[w] = mx;
    }
    __syncthreads();
    if (w == 0) {
        float v = red_sh[l];
        #pragma unroll
        for (int off = 16; off; off >>= 1)
            v = fmaxf(v, __shfl_xor_sync(0xffffffffu, v, off));
        if (l == 0) {
            uint32_t slot = smem_u32(&mbuf[rank]);
            #pragma unroll
            for (int r = 0; r < CSZ; r++)
                st_cluster_f32_addr(mapa_rank(slot, (uint32_t)r), v);
        }
    }
    cluster_sync_all();   // orders max stores AND mbarrier inits cluster-wide
    float m = mbuf[0];
    #pragma unroll
    for (int r = 1; r < CSZ; r++) m = fmaxf(m, mbuf[r]);

    #pragma unroll
    for (int k = 0; k < 16; k++) er[k] = __expf(er[k] - m);

    if (tid < N) d_vec[tid] = 1.0f;   // c = 0 initially
    __syncthreads();

    // ---- hoisted remote addresses
    const int j = tid >> 2;           // column owned for colsum/combine
    const int g = tid & 3;            // depth slice within colsum
    const int p0 = (rank + 1) & (CSZ - 1);
    const int p1 = (rank + 2) & (CSZ - 1);
    const int p2 = (rank + 3) & (CSZ - 1);
    const uint32_t mb_local = smem_u32(&mbar[0]);
    // scatter targets for g==0 lanes (3 peers)
    uint32_t sx0 = 0, sx1 = 0, sx2 = 0;
    if (g == 0) {
        uint32_t la = smem_u32(&xbuf[0][rank][j]);
        sx0 = mapa_rank(la, (uint32_t)p0);
        sx1 = mapa_rank(la, (uint32_t)p1);
        sx2 = mapa_rank(la, (uint32_t)p2);
    }
    // arrive targets for lane 0 of each warp (3 peers)
    uint32_t rm0 = 0, rm1 = 0, rm2 = 0;
    if (l == 0) {
        rm0 = mapa_rank(mb_local, (uint32_t)p0);
        rm1 = mapa_rank(mb_local, (uint32_t)p1);
        rm2 = mapa_rank(mb_local, (uint32_t)p2);
    }

    float rs0 = 1.0f, rs1 = 1.0f;   // 1/rowsum (persist for epilogue)

    #pragma unroll 1
    for (int it = 0; it < NITER; it++) {
        const uint32_t par    = (uint32_t)(it & 1);
        const uint32_t ph     = (uint32_t)((it >> 1) & 1);
        const uint32_t paroff = par * (CSZ * N * 4u);

        // ======== row pass (2 rows/warp) + fused col partials ========
        {
            float4 d0 = *(const float4*)&d_vec[c0];
            float4 d1 = *(const float4*)&d_vec[c0 + 4];
            float s0 = er[0]*d0.x + er[1]*d0.y + er[2]*d0.z + er[3]*d0.w
                     + er[4]*d1.x + er[5]*d1.y + er[6]*d1.z + er[7]*d1.w;
            float s1 = er[8]*d0.x + er[9]*d0.y + er[10]*d0.z + er[11]*d0.w
                     + er[12]*d1.x + er[13]*d1.y + er[14]*d1.z + er[15]*d1.w;
            #pragma unroll
            for (int off = 16; off; off >>= 1) {
                s0 += __shfl_xor_sync(0xffffffffu, s0, off);
                s1 += __shfl_xor_sync(0xffffffffu, s1, off);
            }
            rs0 = __fdividef(1.0f, fmaxf(s0, 1e-30f));
            rs1 = __fdividef(1.0f, fmaxf(s1, 1e-30f));

            float4 q0, q1;
            q0.x = er[0]*rs0 + er[8]*rs1;   q0.y = er[1]*rs0 + er[9]*rs1;
            q0.z = er[2]*rs0 + er[10]*rs1;  q0.w = er[3]*rs0 + er[11]*rs1;
            q1.x = er[4]*rs0 + er[12]*rs1;  q1.y = er[5]*rs0 + er[13]*rs1;
            q1.z = er[6]*rs0 + er[14]*rs1;  q1.w = er[7]*rs0 + er[15]*rs1;
            *(float4*)&ws[w][c0]     = q0;
            *(float4*)&ws[w][c0 + 4] = q1;
        }
        __syncthreads();   // ws complete

        // ======== colsum: 4 threads/col, 8 LDS + 2 shfl (conflict-free) ====
        float p;
        {
            float f0 = ws[g][j]      + ws[g + 4][j];
            float f1 = ws[g + 8][j]  + ws[g + 12][j];
            float f2 = ws[g + 16][j] + ws[g + 20][j];
            float f3 = ws[g + 24][j] + ws[g + 28][j];
            p = (f0 + f1) + (f2 + f3);
            p += __shfl_xor_sync(0xffffffffu, p, 1);
            p += __shfl_xor_sync(0xffffffffu, p, 2);
        }
        // scatter to 3 peers (g==0 lanes: 8 per warp)
        if (g == 0) {
            st_cluster_f32_addr(sx0 + paroff, p);
            st_cluster_f32_addr(sx1 + paroff, p);
            st_cluster_f32_addr(sx2 + paroff, p);
        }
        __syncwarp();      // warp's stores happen-before lane 0's release
        if (l == 0) {
            mbar_arrive_release(rm0 + par * 8);
            mbar_arrive_release(rm1 + par * 8);
            mbar_arrive_release(rm2 + par * 8);
        }

        // ======== combine: own + 3 peers -> d[j] (no intervening barrier) ==
        if (g == 0) {
            mbar_wait(mb_local + par * 8, ph);
            float f = p + xbuf[par][p0][j] + xbuf[par][p1][j] + xbuf[par][p2][j];
            d_vec[j] = __fdividef(1.0f, fmaxf(f, 1e-30f));
        }
        __syncthreads();   // d_vec ready for next iteration
    }

    // ======== epilogue: P = E * e[i] * d[j] (2 rows/warp) ========
    {
        float4 d0 = *(const float4*)&d_vec[c0];
        float4 d1 = *(const float4*)&d_vec[c0 + 4];
        float4 o;
        o.x = er[0]*rs0*d0.x; o.y = er[1]*rs0*d0.y;
        o.z = er[2]*rs0*d0.z; o.w = er[3]*rs0*d0.w;
        *(float4*)(Om + grow * N + c0) = o;
        o.x = er[4]*rs0*d1.x; o.y = er[5]*rs0*d1.y;
        o.z = er[6]*rs0*d1.z; o.w = er[7]*rs0*d1.w;
        *(float4*)(Om + grow * N + c0 + 4) = o;
        o.x = er[8]*rs1*d0.x;  o.y = er[9]*rs1*d0.y;
        o.z = er[10]*rs1*d0.z; o.w = er[11]*rs1*d0.w;
        *(float4*)(Om + (grow + 1) * N + c0) = o;
        o.x = er[12]*rs1*d1.x; o.y = er[13]*rs1*d1.y;
        o.z = er[14]*rs1*d1.z; o.w = er[15]*rs1*d1.w;
        *(float4*)(Om + (grow + 1) * N + c0 + 4) = o;
    }

    // keep all CTAs alive until every in-flight remote store is consumed
    cluster_sync_all();
}

extern "C" void kernel_launch(void* const* d_in, const int* in_sizes, int n_in,
                              void* d_out, int out_size) {
    const float* alpha = (const float*)d_in[0];
    float* out = (float*)d_out;
    sinkhorn_kernel<<<NMAT * CSZ, THREADS>>>(alpha, out);
}

// round 17
// speedup vs baseline: 1.6847x; 1.4899x over previous
#include <cuda_runtime.h>
#include <cstdint>

// Gumbel-Sinkhorn, B=16, N=256, TAU=0.1, 100 iterations.
//
// Primal Sinkhorn-Knopp on the constant matrix E = exp(a/tau - m):
//   e[i] = 1 / sum_j E[i][j] * d[j]     (row normalize)
//   d[j] = 1 / sum_i E[i][j] * e[i]     (col normalize)
//   out  = E[i][j] * e[i] * d[j]
// R14 = R9 (4-CTA cluster, 64 rows/CTA, er[16] row-layout regs, fused col
// partials, 3 CTA barriers, 3 remote arrives) with exactly two deltas:
//   (a) wide colsum: 4 threads/col across all 32 warps (R13's good half),
//   (b) publish via mbarrier.arrive.release.cluster x3 after the CTA
//       barrier -- NO separate fence.acq_rel.cluster (suspected ~500cyc).
// Arrive count stays 3/iter (R13 proved many arrives serialize at the
// destination mbarrier RMW).

namespace {
constexpr int NMAT    = 16;
constexpr int N       = 256;
constexpr int CSZ     = 4;            // CTAs per cluster (one matrix)
constexpr int ROWS    = N / CSZ;      // 64 rows per CTA
constexpr int THREADS = 1024;
constexpr int NWARP   = 32;
constexpr int NITER   = 100;
constexpr int WSL     = 264;          // padded ws row (conflict-free colsum)
constexpr float INV_TAU = 10.0f;
}

__device__ __forceinline__ uint32_t smem_u32(const void* p) {
    return (uint32_t)__cvta_generic_to_shared(p);
}

__device__ __forceinline__ uint32_t mapa_rank(uint32_t laddr, uint32_t rank) {
    uint32_t rem;
    asm volatile("mapa.shared::cluster.u32 %0, %1, %2;" : "=r"(rem) : "r"(laddr), "r"(rank));
    return rem;
}

__device__ __forceinline__ void st_cluster_f32_addr(uint32_t raddr, float v) {
    asm volatile("st.shared::cluster.f32 [%0], %1;" :: "r"(raddr), "f"(v) : "memory");
}

// Remote arrive with cluster-scope RELEASE: cumulativity over the preceding
// __syncthreads publishes ALL CTA threads' prior st.shared::cluster stores.
// Pairs with the acquire in mbar_wait. (Pattern validated correct in R12.)
__device__ __forceinline__ void mbar_arrive_release(uint32_t raddr) {
    asm volatile("mbarrier.arrive.release.cluster.shared::cluster.b64 _, [%0];"
                 :: "r"(raddr) : "memory");
}

__device__ __forceinline__ void mbar_wait(uint32_t addr, uint32_t phase) {
    asm volatile(
        "{\n\t"
        ".reg .pred P;\n\t"
        "WLOOP_%=:\n\t"
        "mbarrier.try_wait.parity.acquire.cluster.shared::cta.b64 P, [%0], %1, 0x989680;\n\t"
        "@P bra WDONE_%=;\n\t"
        "bra WLOOP_%=;\n\t"
        "WDONE_%=:\n\t"
        "}"
        :: "r"(addr), "r"(phase) : "memory");
}

__device__ __forceinline__ void cluster_sync_all() {
    asm volatile("barrier.cluster.arrive.aligned;" ::: "memory");
    asm volatile("barrier.cluster.wait.aligned;" ::: "memory");
}

__global__ void __launch_bounds__(THREADS, 1) __cluster_dims__(CSZ, 1, 1)
sinkhorn_kernel(const float* __restrict__ A, float* __restrict__ Out)
{
    __shared__ __align__(16) float d_vec[N];
    __shared__ __align__(16) float ws[NWARP][WSL];   // col partials, ~33.8 KB
    __shared__ __align__(16) float xbuf[2][CSZ][N];  // peer partials, 8 KB
    __shared__ __align__(8) unsigned long long mbar[2];
    __shared__ float red_sh[NWARP];
    __shared__ float mbuf[CSZ];

    const int tid  = threadIdx.x;
    const int w    = tid >> 5;
    const int l    = tid & 31;
    const int rank = blockIdx.x & (CSZ - 1);
    const int b    = blockIdx.x >> 2;

    const float* Am = A   + (size_t)b * N * N;
    float*       Om = Out + (size_t)b * N * N;

    if (tid == 0) {
        asm volatile("mbarrier.init.shared.b64 [%0], %1;"
                     :: "r"(smem_u32(&mbar[0])), "r"(CSZ - 1) : "memory");
        asm volatile("mbarrier.init.shared.b64 [%0], %1;"
                     :: "r"(smem_u32(&mbar[1])), "r"(CSZ - 1) : "memory");
        asm volatile("fence.mbarrier_init.release.cluster;" ::: "memory");
    }

    // ---- row layout: warp w owns local rows {2w, 2w+1}; lane l cols [8l,8l+8)
    const int r0   = 2 * w;
    const int c0   = l * 8;
    const int grow = rank * ROWS + r0;

    float er[16];  // [row r0: 8 cols][row r0+1: 8 cols]
    {
        float4 a0 = *(const float4*)(Am + grow * N + c0);
        float4 a1 = *(const float4*)(Am + grow * N + c0 + 4);
        float4 b0 = *(const float4*)(Am + (grow + 1) * N + c0);
        float4 b1 = *(const float4*)(Am + (grow + 1) * N + c0 + 4);
        er[0]=a0.x; er[1]=a0.y; er[2]=a0.z;  er[3]=a0.w;
        er[4]=a1.x; er[5]=a1.y; er[6]=a1.z;  er[7]=a1.w;
        er[8]=b0.x; er[9]=b0.y; er[10]=b0.z; er[11]=b0.w;
        er[12]=b1.x; er[13]=b1.y; er[14]=b1.z; er[15]=b1.w;
        #pragma unroll
        for (int k = 0; k < 16; k++) er[k] *= INV_TAU;
    }

    // ---- global per-matrix max m (stable E = exp(a/tau - m))
    {
        float mx = er[0];
        #pragma unroll
        for (int k = 1; k < 16; k++) mx = fmaxf(mx, er[k]);
        #pragma unroll
        for (int off = 16; off; off >>= 1)
            mx = fmaxf(mx, __shfl_xor_sync(0xffffffffu, mx, off));
        if (l == 0) red_sh[w] = mx;
    }
    __syncthreads();
    if (w == 0) {
        float v = red_sh[l];
        #pragma unroll
        for (int off = 16; off; off >>= 1)
            v = fmaxf(v, __shfl_xor_sync(0xffffffffu, v, off));
        if (l == 0) {
            uint32_t slot = smem_u32(&mbuf[rank]);
            #pragma unroll
            for (int r = 0; r < CSZ; r++)
                st_cluster_f32_addr(mapa_rank(slot, (uint32_t)r), v);
        }
    }
    cluster_sync_all();   // orders max stores AND mbarrier inits cluster-wide
    float m = mbuf[0];
    #pragma unroll
    for (int r = 1; r < CSZ; r++) m = fmaxf(m, mbuf[r]);

    #pragma unroll
    for (int k = 0; k < 16; k++) er[k] = __expf(er[k] - m);

    if (tid < N) d_vec[tid] = 1.0f;   // c = 0 initially
    __syncthreads();

    // ---- hoisted remote addresses
    const int j = tid >> 2;           // column owned for colsum/combine
    const int g = tid & 3;            // depth slice within colsum
    const int p0 = (rank + 1) & (CSZ - 1);
    const int p1 = (rank + 2) & (CSZ - 1);
    const int p2 = (rank + 3) & (CSZ - 1);
    const uint32_t mb_local = smem_u32(&mbar[0]);
    // scatter targets for g==0 lanes (3 peers)
    uint32_t sx0 = 0, sx1 = 0, sx2 = 0;
    if (g == 0) {
        uint32_t la = smem_u32(&xbuf[0][rank][j]);
        sx0 = mapa_rank(la, (uint32_t)p0);
        sx1 = mapa_rank(la, (uint32_t)p1);
        sx2 = mapa_rank(la, (uint32_t)p2);
    }
    // arrive targets for warp 0 lanes 0..2 (one peer each)
    uint32_t rmb = 0;
    if (w == 0 && l < CSZ - 1)
        rmb = mapa_rank(mb_local, (uint32_t)((rank + 1 + l) & (CSZ - 1)));

    float rs0 = 1.0f, rs1 = 1.0f;   // 1/rowsum (persist for epilogue)

    #pragma unroll 1
    for (int it = 0; it < NITER; it++) {
        const uint32_t par    = (uint32_t)(it & 1);
        const uint32_t ph     = (uint32_t)((it >> 1) & 1);
        const uint32_t paroff = par * (CSZ * N * 4u);

        // ======== row pass (2 rows/warp) + fused col partials ========
        {
            float4 d0 = *(const float4*)&d_vec[c0];
            float4 d1 = *(const float4*)&d_vec[c0 + 4];
            float s0 = er[0]*d0.x + er[1]*d0.y + er[2]*d0.z + er[3]*d0.w
                     + er[4]*d1.x + er[5]*d1.y + er[6]*d1.z + er[7]*d1.w;
            float s1 = er[8]*d0.x + er[9]*d0.y + er[10]*d0.z + er[11]*d0.w
                     + er[12]*d1.x + er[13]*d1.y + er[14]*d1.z + er[15]*d1.w;
            #pragma unroll
            for (int off = 16; off; off >>= 1) {
                s0 += __shfl_xor_sync(0xffffffffu, s0, off);
                s1 += __shfl_xor_sync(0xffffffffu, s1, off);
            }
            rs0 = __fdividef(1.0f, fmaxf(s0, 1e-30f));
            rs1 = __fdividef(1.0f, fmaxf(s1, 1e-30f));

            float4 q0, q1;
            q0.x = er[0]*rs0 + er[8]*rs1;   q0.y = er[1]*rs0 + er[9]*rs1;
            q0.z = er[2]*rs0 + er[10]*rs1;  q0.w = er[3]*rs0 + er[11]*rs1;
            q1.x = er[4]*rs0 + er[12]*rs1;  q1.y = er[5]*rs0 + er[13]*rs1;
            q1.z = er[6]*rs0 + er[14]*rs1;  q1.w = er[7]*rs0 + er[15]*rs1;
            *(float4*)&ws[w][c0]     = q0;
            *(float4*)&ws[w][c0 + 4] = q1;
        }
        __syncthreads();   // (1) ws complete

        // ======== wide colsum: 4 threads/col, 8 LDS + 2 shfl ========
        // ws[g+4i][j]: bank = (8g + j) mod 32 -> conflict-free (WSL=264)
        float p;
        {
            float f0 = ws[g][j]      + ws[g + 4][j];
            float f1 = ws[g + 8][j]  + ws[g + 12][j];
            float f2 = ws[g + 16][j] + ws[g + 20][j];
            float f3 = ws[g + 24][j] + ws[g + 28][j];
            p = (f0 + f1) + (f2 + f3);
            p += __shfl_xor_sync(0xffffffffu, p, 1);
            p += __shfl_xor_sync(0xffffffffu, p, 2);
        }
        // scatter to 3 peers (g==0 lanes: 8 per warp, all warps)
        if (g == 0) {
            st_cluster_f32_addr(sx0 + paroff, p);
            st_cluster_f32_addr(sx1 + paroff, p);
            st_cluster_f32_addr(sx2 + paroff, p);
        }
        __syncthreads();   // (2) all scatter stores happen-before the arrives

        // publish: 3 release-arrives (NO separate cluster fence)
        if (w == 0 && l < CSZ - 1)
            mbar_arrive_release(rmb + par * 8);

        // ======== combine: own + 3 peers -> d[j] ========
        if (g == 0) {
            mbar_wait(mb_local + par * 8, ph);
            float f = p + xbuf[par][p0][j] + xbuf[par][p1][j] + xbuf[par][p2][j];
            d_vec[j] = __fdividef(1.0f, fmaxf(f, 1e-30f));
        }
        __syncthreads();   // (3) d_vec ready for next iteration
    }

    // ======== epilogue: P = E * e[i] * d[j] (2 rows/warp) ========
    {
        float4 d0 = *(const float4*)&d_vec[c0];
        float4 d1 = *(const float4*)&d_vec[c0 + 4];
        float4 o;
        o.x = er[0]*rs0*d0.x; o.y = er[1]*rs0*d0.y;
        o.z = er[2]*rs0*d0.z; o.w = er[3]*rs0*d0.w;
        *(float4*)(Om + grow * N + c0) = o;
        o.x = er[4]*rs0*d1.x; o.y = er[5]*rs0*d1.y;
        o.z = er[6]*rs0*d1.z; o.w = er[7]*rs0*d1.w;
        *(float4*)(Om + grow * N + c0 + 4) = o;
        o.x = er[8]*rs1*d0.x;  o.y = er[9]*rs1*d0.y;
        o.z = er[10]*rs1*d0.z; o.w = er[11]*rs1*d0.w;
        *(float4*)(Om + (grow + 1) * N + c0) = o;
        o.x = er[12]*rs1*d1.x; o.y = er[13]*rs1*d1.y;
        o.z = er[14]*rs1*d1.z; o.w = er[15]*rs1*d1.w;
        *(float4*)(Om + (grow + 1) * N + c0 + 4) = o;
    }

    // keep all CTAs alive until every in-flight remote store is consumed
    cluster_sync_all();
}

extern "C" void kernel_launch(void* const* d_in, const int* in_sizes, int n_in,
                              void* d_out, int out_size) {
    const float* alpha = (const float*)d_in[0];
    float* out = (float*)d_out;
    sinkhorn_kernel<<<NMAT * CSZ, THREADS>>>(alpha, out);
}